// round 6
// baseline (speedup 1.0000x reference)
#include <cuda_runtime.h>
#include <math.h>

#define BB 8
#define LL 8192
#define DD 768
#define NE 128
#define NPAIR (NE*(NE-1)/2)   // 8128
#define NP4   (DD/4)          // 192 float4 per row

#define KSPLIT 16
#define KC     (DD/KSPLIT)    // 48
#define PITCH  132

typedef unsigned long long ull;

// Scratch (no allocations allowed)
__device__ float    g_emb[BB*NE*DD];   // normalized embeddings
__device__ float    g_sim[BB*NE*NE];   // cosine sims (atomic-accumulated)
__device__ float    g_mlp[4];          // collapsed MLP constants
__device__ int      g_flag;            // nonzero -> full-MLP fallback
__device__ unsigned g_done[BB];        // per-batch arrival counters (self-reset)

// ---- packed f32x2 helpers ------------------------------------------------
__device__ __forceinline__ void fma2(ull &d, ull a, ull b) {
    asm("fma.rn.f32x2 %0, %1, %2, %0;" : "+l"(d) : "l"(a), "l"(b));
}
__device__ __forceinline__ ull pack2(float v) {
    ull r; unsigned u = __float_as_uint(v);
    asm("mov.b64 %0, {%1, %1};" : "=l"(r) : "r"(u));
    return r;
}
__device__ __forceinline__ void unpack2(ull v, float &lo, float &hi) {
    unsigned a, b;
    asm("mov.b64 {%0, %1}, %2;" : "=r"(a), "=r"(b) : "l"(v));
    lo = __uint_as_float(a); hi = __uint_as_float(b);
}

// ---------------------------------------------------------------------------
// K1: blocks 0..1023: span mean pool -> normalized embedding (192 thr/span).
//     Also zeroes g_sim. Block 1024: collapse scalar-input MLP.
// ---------------------------------------------------------------------------
__global__ void __launch_bounds__(192)
k_pool(const float* __restrict__ x,
       const int*   __restrict__ starts,
       const int*   __restrict__ lengths,
       const float* __restrict__ W1,
       const float* __restrict__ b1,
       const float* __restrict__ W2) {
    const int blk = blockIdx.x;
    const int tid = threadIdx.x;         // 192

    if (blk == 1024) {                   // ---- MLP collapse ----
        __shared__ float r0[128], r1[128], r2[128], r3[128];
        __shared__ int   rf[128];
        if (tid < 128) {
            const float w1  = W1[tid];
            const float w20 = W2[2*tid], w21 = W2[2*tid+1];
            r0[tid] = (w1 > 0.f) ? w1*w20 : 0.f;
            r1[tid] = (w1 > 0.f) ? w1*w21 : 0.f;
            r2[tid] = (w1 < 0.f) ? w1*w20 : 0.f;
            r3[tid] = (w1 < 0.f) ? w1*w21 : 0.f;
            rf[tid] = (b1[tid] != 0.f) ? 1 : 0;
        }
        __syncthreads();
        #pragma unroll
        for (int o = 64; o > 0; o >>= 1) {
            if (tid < o) {
                r0[tid]+=r0[tid+o]; r1[tid]+=r1[tid+o];
                r2[tid]+=r2[tid+o]; r3[tid]+=r3[tid+o];
                rf[tid]|=rf[tid+o];
            }
            __syncthreads();
        }
        if (tid == 0) {
            g_mlp[0]=r0[0]; g_mlp[1]=r1[0]; g_mlp[2]=r2[0]; g_mlp[3]=r3[0];
            g_flag = rf[0];
        }
        return;
    }

    // ---- span pooling ----
    const int b = blk >> 7;
    if (tid < 32)                        // zero sim accumulator (32 f4 each)
        __stcg(&((float4*)g_sim)[blk*32 + tid], make_float4(0.f,0.f,0.f,0.f));

    const int s   = starts[blk];
    const int len = lengths[blk];
    const float inv_len = 1.0f / (float)len;
    const float4* base = (const float4*)x + ((long)b*LL + s)*NP4 + tid;

    float4 a0 = make_float4(0,0,0,0), a1 = a0, a2 = a0, a3 = a0;
    #pragma unroll
    for (int t = 0; t < 16; t += 4) {
        if (t   < len) { float4 v = base[(t  )*NP4]; a0.x+=v.x; a0.y+=v.y; a0.z+=v.z; a0.w+=v.w; }
        if (t+1 < len) { float4 v = base[(t+1)*NP4]; a1.x+=v.x; a1.y+=v.y; a1.z+=v.z; a1.w+=v.w; }
        if (t+2 < len) { float4 v = base[(t+2)*NP4]; a2.x+=v.x; a2.y+=v.y; a2.z+=v.z; a2.w+=v.w; }
        if (t+3 < len) { float4 v = base[(t+3)*NP4]; a3.x+=v.x; a3.y+=v.y; a3.z+=v.z; a3.w+=v.w; }
    }
    float4 e;
    e.x = (a0.x+a1.x+a2.x+a3.x)*inv_len;
    e.y = (a0.y+a1.y+a2.y+a3.y)*inv_len;
    e.z = (a0.z+a1.z+a2.z+a3.z)*inv_len;
    e.w = (a0.w+a1.w+a2.w+a3.w)*inv_len;

    float ss = e.x*e.x + e.y*e.y + e.z*e.z + e.w*e.w;
    #pragma unroll
    for (int o = 16; o > 0; o >>= 1) ss += __shfl_xor_sync(0xffffffffu, ss, o);

    __shared__ float wsum[6];
    __shared__ float s_inv;
    if ((tid & 31) == 0) wsum[tid >> 5] = ss;
    __syncthreads();
    if (tid == 0)
        s_inv = 1.0f / sqrtf(wsum[0]+wsum[1]+wsum[2]+wsum[3]+wsum[4]+wsum[5]);
    __syncthreads();
    const float inv = s_inv;
    ((float4*)g_emb)[(long)blk*NP4 + tid] =
        make_float4(e.x*inv, e.y*inv, e.z*inv, e.w*inv);
}

// ---------------------------------------------------------------------------
// K2: split-K syrk (grid KSPLITxBB); per-batch LAST-ARRIVER block then does
//     fp64 stats for its batch and classifies that batch's 8128 pairs.
// ---------------------------------------------------------------------------
__global__ void __launch_bounds__(256, 1)
k_sim(const int*   __restrict__ hts,
      const float* __restrict__ thr,
      const float* __restrict__ W1,
      const float* __restrict__ b1,
      const float* __restrict__ W2,
      const float* __restrict__ b2,
      float*       __restrict__ out) {
    const int b  = blockIdx.y;
    const int kc = blockIdx.x;
    const int tid = threadIdx.x;
    const int lane = tid & 31;
    const int wrp  = tid >> 5;
    const int ty = tid >> 4, tx = tid & 15;
    const int i8 = ty*8, j8 = tx*8;

    __shared__ __align__(16) float At[KC][PITCH];

    // ---- load tile transposed ----
    const float4* Eb4 = (const float4*)g_emb + (long)b*NE*NP4 + kc*(KC/4);
    #pragma unroll
    for (int e = 0; e < 6; ++e) {
        const int idx = tid + e*256;
        const int j  = idx & 127;
        const int kg = idx >> 7;
        float4 v = Eb4[(long)j*NP4 + kg];
        At[4*kg+0][j] = v.x;
        At[4*kg+1][j] = v.y;
        At[4*kg+2][j] = v.z;
        At[4*kg+3][j] = v.w;
    }
    __syncthreads();

    // ---- 8x8 FFMA2 syrk over 48-wide K chunk ----
    ull c[8][4];
    #pragma unroll
    for (int r = 0; r < 8; ++r)
        #pragma unroll
        for (int q = 0; q < 4; ++q) c[r][q] = 0ull;

    #pragma unroll 4
    for (int kk = 0; kk < KC; ++kk) {
        const float4 alo = *(const float4*)&At[kk][i8];
        const float4 ahi = *(const float4*)&At[kk][i8 + 4];
        ull a2[8];
        a2[0]=pack2(alo.x); a2[1]=pack2(alo.y); a2[2]=pack2(alo.z); a2[3]=pack2(alo.w);
        a2[4]=pack2(ahi.x); a2[5]=pack2(ahi.y); a2[6]=pack2(ahi.z); a2[7]=pack2(ahi.w);
        const ulonglong2 bv0 = *(const ulonglong2*)&At[kk][j8];
        const ulonglong2 bv1 = *(const ulonglong2*)&At[kk][j8 + 4];
        ull bb[4] = {bv0.x, bv0.y, bv1.x, bv1.y};
        #pragma unroll
        for (int r = 0; r < 8; ++r)
            #pragma unroll
            for (int q = 0; q < 4; ++q) fma2(c[r][q], a2[r], bb[q]);
    }

    float* S = g_sim + ((long)b*NE + i8)*NE + j8;
    #pragma unroll
    for (int r = 0; r < 8; ++r)
        #pragma unroll
        for (int q = 0; q < 4; ++q) {
            float lo, hi;
            unpack2(c[r][q], lo, hi);
            atomicAdd(&S[(long)r*NE + 2*q    ], lo);
            atomicAdd(&S[(long)r*NE + 2*q + 1], hi);
        }

    // ---- arrival: last of the 16 blocks for batch b finalizes ----
    __threadfence();                     // my atomics -> visible before arrival
    __shared__ int is_last;
    if (tid == 0) {
        const unsigned arr = atomicAdd(&g_done[b], 1u);
        is_last = (arr == KSPLIT - 1);
        if (is_last) g_done[b] = 0u;     // reset for next replay
    }
    __syncthreads();
    if (!is_last) return;
    __threadfence();                     // acquire: others' atomics visible

    // ---- per-batch fp64 stats (16384 values) ----
    const float4* S4 = (const float4*)(g_sim + (long)b*NE*NE);
    double s = 0.0, qq = 0.0;
    #pragma unroll
    for (int it = 0; it < 16; ++it) {
        const float4 v = __ldcg(&S4[tid + it*256]);
        s  += (double)v.x + (double)v.y + (double)v.z + (double)v.w;
        qq += (double)v.x*v.x + (double)v.y*v.y
            + (double)v.z*v.z + (double)v.w*v.w;
    }
    #pragma unroll
    for (int o = 16; o > 0; o >>= 1) {
        s  += __shfl_xor_sync(0xffffffffu, s,  o);
        qq += __shfl_xor_sync(0xffffffffu, qq, o);
    }
    __shared__ double sS[8], sQ[8];
    __shared__ float  s_cinv;
    if (lane == 0) { sS[wrp] = s; sQ[wrp] = qq; }
    __syncthreads();
    if (tid == 0) {
        double ts = 0.0, tq = 0.0;
        #pragma unroll
        for (int w = 0; w < 8; ++w) { ts += sS[w]; tq += sQ[w]; }
        const double n  = (double)(NE*NE);
        const double sd = sqrt((tq - ts*ts/n) / (n - 1.0));
        s_cinv = 1.0f / ((float)sd + 1e-5f);
    }
    __syncthreads();

    // ---- classify this batch's 8128 pairs (32 per thread) ----
    const float cinv = s_cinv;
    const float t0   = __ldg(thr);
    const float b20  = __ldg(&b2[0]), b21 = __ldg(&b2[1]);
    const int   flg  = __ldcg(&g_flag);
    const float m0p  = __ldcg(&g_mlp[0]), m1p = __ldcg(&g_mlp[1]);
    const float m0n  = __ldcg(&g_mlp[2]), m1n = __ldcg(&g_mlp[3]);

    const int2*  H = (const int2*)hts + (long)b*NPAIR;
    float2*      O = (float2*)out + (long)b*NPAIR;
    const float* Sb = g_sim + (long)b*NE*NE;

    #pragma unroll 4
    for (int p = tid; p < NPAIR; p += 256) {
        const int2 ht = H[p];
        const float sim = __ldcg(&Sb[ht.x*NE + ht.y]);
        const float pv  = (sim - t0) * cinv;
        float o0, o1;
        if (flg == 0) {
            o0 = fmaf(pv, (pv > 0.f) ? m0p : m0n, b20);
            o1 = fmaf(pv, (pv > 0.f) ? m1p : m1n, b21);
        } else {
            o0 = b20; o1 = b21;
            for (int k = 0; k < 128; ++k) {
                const float h = fmaxf(fmaf(pv, __ldg(&W1[k]), __ldg(&b1[k])), 0.f);
                o0 = fmaf(h, __ldg(&W2[2*k  ]), o0);
                o1 = fmaf(h, __ldg(&W2[2*k+1]), o1);
            }
        }
        O[p] = make_float2(o0, o1);
    }
}

// ---------------------------------------------------------------------------
extern "C" void kernel_launch(void* const* d_in, const int* in_sizes, int n_in,
                              void* d_out, int out_size) {
    const float* x       = (const float*)d_in[0];
    const int*   starts  = (const int*)  d_in[1];
    const int*   lengths = (const int*)  d_in[2];
    const int*   hts     = (const int*)  d_in[3];
    const float* thr     = (const float*)d_in[4];
    const float* W1      = (const float*)d_in[5];
    const float* b1      = (const float*)d_in[6];
    const float* W2      = (const float*)d_in[7];
    const float* b2      = (const float*)d_in[8];
    float* out = (float*)d_out;

    k_pool<<<BB*NE + 1, 192>>>(x, starts, lengths, W1, b1, W2);
    dim3 gsim(KSPLIT, BB);
    k_sim<<<gsim, 256>>>(hts, thr, W1, b1, W2, b2, out);
}

// round 7
// speedup vs baseline: 1.4134x; 1.4134x over previous
#include <cuda_runtime.h>
#include <math.h>

#define BB 8
#define LL 8192
#define DD 768
#define NE 128
#define NPAIR (NE*(NE-1)/2)   // 8128
#define NP4   (DD/4)          // 192 float4 per row

#define KSPLIT 16
#define KC     (DD/KSPLIT)    // 48
#define PITCH  132

typedef unsigned long long ull;

// Scratch (no allocations allowed)
__device__ float g_emb[BB*NE*DD];          // normalized embeddings (3 MB)
__device__ float g_par[KSPLIT][BB*NE*NE];  // split-K partial sims (8 MB)
__device__ float g_cinv[BB];               // 1/(std+1e-5)
__device__ float g_mlp[4];                 // collapsed MLP constants
__device__ int   g_flag;                   // nonzero -> full-MLP fallback
__device__ int   g_ready[BB];              // per-batch cinv-ready flags

// ---- packed f32x2 helpers ------------------------------------------------
__device__ __forceinline__ void fma2(ull &d, ull a, ull b) {
    asm("fma.rn.f32x2 %0, %1, %2, %0;" : "+l"(d) : "l"(a), "l"(b));
}
__device__ __forceinline__ ull pack2(float v) {
    ull r; unsigned u = __float_as_uint(v);
    asm("mov.b64 %0, {%1, %1};" : "=l"(r) : "r"(u));
    return r;
}
__device__ __forceinline__ void unpack2(ull v, float &lo, float &hi) {
    unsigned a, b;
    asm("mov.b64 {%0, %1}, %2;" : "=r"(a), "=r"(b) : "l"(v));
    lo = __uint_as_float(a); hi = __uint_as_float(b);
}

// ---------------------------------------------------------------------------
// K1: blocks 0..1023: span mean pool -> normalized embedding (192 thr/span).
//     Block 1024: collapse scalar-input MLP. Block 0 also resets ready flags.
// ---------------------------------------------------------------------------
__global__ void __launch_bounds__(192)
k_pool(const float* __restrict__ x,
       const int*   __restrict__ starts,
       const int*   __restrict__ lengths,
       const float* __restrict__ W1,
       const float* __restrict__ b1,
       const float* __restrict__ W2) {
    const int blk = blockIdx.x;
    const int tid = threadIdx.x;         // 192

    if (blk == 1024) {                   // ---- MLP collapse ----
        __shared__ float r0[128], r1[128], r2[128], r3[128];
        __shared__ int   rf[128];
        if (tid < 128) {
            const float w1  = W1[tid];
            const float w20 = W2[2*tid], w21 = W2[2*tid+1];
            r0[tid] = (w1 > 0.f) ? w1*w20 : 0.f;
            r1[tid] = (w1 > 0.f) ? w1*w21 : 0.f;
            r2[tid] = (w1 < 0.f) ? w1*w20 : 0.f;
            r3[tid] = (w1 < 0.f) ? w1*w21 : 0.f;
            rf[tid] = (b1[tid] != 0.f) ? 1 : 0;
        }
        __syncthreads();
        #pragma unroll
        for (int o = 64; o > 0; o >>= 1) {
            if (tid < o) {
                r0[tid]+=r0[tid+o]; r1[tid]+=r1[tid+o];
                r2[tid]+=r2[tid+o]; r3[tid]+=r3[tid+o];
                rf[tid]|=rf[tid+o];
            }
            __syncthreads();
        }
        if (tid == 0) {
            g_mlp[0]=r0[0]; g_mlp[1]=r1[0]; g_mlp[2]=r2[0]; g_mlp[3]=r3[0];
            g_flag = rf[0];
        }
        return;
    }

    if (blk == 0 && tid < BB) g_ready[tid] = 0;   // reset flag protocol

    // ---- span pooling ----
    const int b   = blk >> 7;
    const int s   = starts[blk];
    const int len = lengths[blk];
    const float inv_len = 1.0f / (float)len;
    const float4* base = (const float4*)x + ((long)b*LL + s)*NP4 + tid;

    float4 a0 = make_float4(0,0,0,0), a1 = a0, a2 = a0, a3 = a0;
    #pragma unroll
    for (int t = 0; t < 16; t += 4) {
        if (t   < len) { float4 v = base[(t  )*NP4]; a0.x+=v.x; a0.y+=v.y; a0.z+=v.z; a0.w+=v.w; }
        if (t+1 < len) { float4 v = base[(t+1)*NP4]; a1.x+=v.x; a1.y+=v.y; a1.z+=v.z; a1.w+=v.w; }
        if (t+2 < len) { float4 v = base[(t+2)*NP4]; a2.x+=v.x; a2.y+=v.y; a2.z+=v.z; a2.w+=v.w; }
        if (t+3 < len) { float4 v = base[(t+3)*NP4]; a3.x+=v.x; a3.y+=v.y; a3.z+=v.z; a3.w+=v.w; }
    }
    float4 e;
    e.x = (a0.x+a1.x+a2.x+a3.x)*inv_len;
    e.y = (a0.y+a1.y+a2.y+a3.y)*inv_len;
    e.z = (a0.z+a1.z+a2.z+a3.z)*inv_len;
    e.w = (a0.w+a1.w+a2.w+a3.w)*inv_len;

    float ss = e.x*e.x + e.y*e.y + e.z*e.z + e.w*e.w;
    #pragma unroll
    for (int o = 16; o > 0; o >>= 1) ss += __shfl_xor_sync(0xffffffffu, ss, o);

    __shared__ float wsum[6];
    __shared__ float s_inv;
    if ((tid & 31) == 0) wsum[tid >> 5] = ss;
    __syncthreads();
    if (tid == 0)
        s_inv = 1.0f / sqrtf(wsum[0]+wsum[1]+wsum[2]+wsum[3]+wsum[4]+wsum[5]);
    __syncthreads();
    const float inv = s_inv;
    ((float4*)g_emb)[(long)blk*NP4 + tid] =
        make_float4(e.x*inv, e.y*inv, e.z*inv, e.w*inv);
}

// ---------------------------------------------------------------------------
// K2: split-K syrk, grid (KSPLIT, BB). 8x8 per-thread FFMA2 tiles over a
//     48-wide K chunk; PLAIN float4 stores of the partial (no atomics).
// ---------------------------------------------------------------------------
__global__ void __launch_bounds__(256, 1) k_sim(void) {
    const int b  = blockIdx.y;
    const int kc = blockIdx.x;
    const int tid = threadIdx.x;
    const int ty = tid >> 4, tx = tid & 15;
    const int i8 = ty*8, j8 = tx*8;

    __shared__ __align__(16) float At[KC][PITCH];   // [k][i], transposed

    const float4* Eb4 = (const float4*)g_emb + (long)b*NE*NP4 + kc*(KC/4);
    #pragma unroll
    for (int e = 0; e < 6; ++e) {
        const int idx = tid + e*256;     // 0..1535
        const int j  = idx & 127;
        const int kg = idx >> 7;         // 0..11
        float4 v = Eb4[(long)j*NP4 + kg];
        At[4*kg+0][j] = v.x;
        At[4*kg+1][j] = v.y;
        At[4*kg+2][j] = v.z;
        At[4*kg+3][j] = v.w;
    }
    __syncthreads();

    ull c[8][4];
    #pragma unroll
    for (int r = 0; r < 8; ++r)
        #pragma unroll
        for (int q = 0; q < 4; ++q) c[r][q] = 0ull;

    #pragma unroll 4
    for (int kk = 0; kk < KC; ++kk) {
        const float4 alo = *(const float4*)&At[kk][i8];
        const float4 ahi = *(const float4*)&At[kk][i8 + 4];
        ull a2[8];
        a2[0]=pack2(alo.x); a2[1]=pack2(alo.y); a2[2]=pack2(alo.z); a2[3]=pack2(alo.w);
        a2[4]=pack2(ahi.x); a2[5]=pack2(ahi.y); a2[6]=pack2(ahi.z); a2[7]=pack2(ahi.w);
        const ulonglong2 bv0 = *(const ulonglong2*)&At[kk][j8];
        const ulonglong2 bv1 = *(const ulonglong2*)&At[kk][j8 + 4];
        ull bb[4] = {bv0.x, bv0.y, bv1.x, bv1.y};
        #pragma unroll
        for (int r = 0; r < 8; ++r)
            #pragma unroll
            for (int q = 0; q < 4; ++q) fma2(c[r][q], a2[r], bb[q]);
    }

    float* P = g_par[kc] + (long)b*NE*NE + i8*NE + j8;
    #pragma unroll
    for (int r = 0; r < 8; ++r) {
        float l0,h0,l1,h1,l2,h2,l3,h3;
        unpack2(c[r][0], l0, h0);
        unpack2(c[r][1], l1, h1);
        unpack2(c[r][2], l2, h2);
        unpack2(c[r][3], l3, h3);
        ((float4*)(P + (long)r*NE))[0] = make_float4(l0, h0, l1, h1);
        ((float4*)(P + (long)r*NE))[1] = make_float4(l2, h2, l3, h3);
    }
}

// ---------------------------------------------------------------------------
// K3: fused stats + classify.
//     Blocks 0..7: per-batch stats over summed partials -> g_cinv, set ready.
//     Blocks 8..261: compute pair's partial sum FIRST, then spin on ready,
//     finalize + classify. All 262 blocks co-resident -> no deadlock.
// ---------------------------------------------------------------------------
__global__ void __launch_bounds__(256)
k_statscls(const int*   __restrict__ hts,
           const float* __restrict__ thr,
           const float* __restrict__ W1,
           const float* __restrict__ b1,
           const float* __restrict__ W2,
           const float* __restrict__ b2,
           float*       __restrict__ out) {
    const int blk = blockIdx.x;
    const int tid = threadIdx.x;         // 256

    if (blk < BB) {
        // ---- per-batch stats ----
        const int b = blk;
        float s = 0.f, q = 0.f;
        #pragma unroll 4
        for (int it = 0; it < 16; ++it) {
            const int f = tid + it*256;  // float4 index within batch slice
            float4 acc = make_float4(0.f, 0.f, 0.f, 0.f);
            #pragma unroll
            for (int kc = 0; kc < KSPLIT; ++kc) {
                const float4 v = __ldcg(&((const float4*)(g_par[kc] + (long)b*NE*NE))[f]);
                acc.x+=v.x; acc.y+=v.y; acc.z+=v.z; acc.w+=v.w;
            }
            s += acc.x + acc.y + acc.z + acc.w;
            q += acc.x*acc.x + acc.y*acc.y + acc.z*acc.z + acc.w*acc.w;
        }
        double ds = (double)s, dq = (double)q;
        #pragma unroll
        for (int o = 16; o > 0; o >>= 1) {
            ds += __shfl_xor_sync(0xffffffffu, ds, o);
            dq += __shfl_xor_sync(0xffffffffu, dq, o);
        }
        __shared__ double sS[8], sQ[8];
        if ((tid & 31) == 0) { sS[tid >> 5] = ds; sQ[tid >> 5] = dq; }
        __syncthreads();
        if (tid == 0) {
            double ts = 0.0, tq = 0.0;
            #pragma unroll
            for (int w = 0; w < 8; ++w) { ts += sS[w]; tq += sQ[w]; }
            const double n  = (double)(NE*NE);
            const double sd = sqrt((tq - ts*ts/n) / (n - 1.0));
            g_cinv[b] = 1.0f / ((float)sd + 1e-5f);
            __threadfence();
            *(volatile int*)&g_ready[b] = 1;
        }
        return;
    }

    // ---- classify: one pair per thread (254*256 = 65024 exactly) ----
    const int gp = (blk - BB)*256 + tid;
    const int b  = gp / NPAIR;
    const int2 ht = ((const int2*)hts)[gp];
    const long off = (long)b*NE*NE + ht.x*NE + ht.y;

    float s16 = 0.f;                     // partial sum BEFORE waiting on cinv
    #pragma unroll
    for (int kc = 0; kc < KSPLIT; ++kc) s16 += __ldcg(&g_par[kc][off]);

    if (*(volatile int*)&g_ready[b] == 0) {
        while (*(volatile int*)&g_ready[b] == 0) __nanosleep(32);
    }
    __threadfence();                     // make g_cinv load observe the write

    const float cinv = __ldcg(&g_cinv[b]);
    const float pv   = (s16 - __ldg(thr)) * cinv;
    const float b20  = __ldg(&b2[0]), b21 = __ldg(&b2[1]);

    float o0, o1;
    if (g_flag == 0) {
        const float m0 = (pv > 0.f) ? g_mlp[0] : g_mlp[2];
        const float m1 = (pv > 0.f) ? g_mlp[1] : g_mlp[3];
        o0 = fmaf(pv, m0, b20);
        o1 = fmaf(pv, m1, b21);
    } else {
        o0 = b20; o1 = b21;
        #pragma unroll 8
        for (int k = 0; k < 128; ++k) {
            const float h = fmaxf(fmaf(pv, __ldg(&W1[k]), __ldg(&b1[k])), 0.f);
            o0 = fmaf(h, __ldg(&W2[2*k  ]), o0);
            o1 = fmaf(h, __ldg(&W2[2*k+1]), o1);
        }
    }
    ((float2*)out)[gp] = make_float2(o0, o1);
}

// ---------------------------------------------------------------------------
extern "C" void kernel_launch(void* const* d_in, const int* in_sizes, int n_in,
                              void* d_out, int out_size) {
    const float* x       = (const float*)d_in[0];
    const int*   starts  = (const int*)  d_in[1];
    const int*   lengths = (const int*)  d_in[2];
    const int*   hts     = (const int*)  d_in[3];
    const float* thr     = (const float*)d_in[4];
    const float* W1      = (const float*)d_in[5];
    const float* b1      = (const float*)d_in[6];
    const float* W2      = (const float*)d_in[7];
    const float* b2      = (const float*)d_in[8];
    float* out = (float*)d_out;

    k_pool<<<BB*NE + 1, 192>>>(x, starts, lengths, W1, b1, W2);
    dim3 gsim(KSPLIT, BB);
    k_sim<<<gsim, 256>>>();
    k_statscls<<<BB + 254, 256>>>(hts, thr, W1, b1, W2, b2, out);
}

// round 8
// speedup vs baseline: 2.0987x; 1.4848x over previous
#include <cuda_runtime.h>
#include <math.h>

#define BB 8
#define LL 8192
#define DD 768
#define NE 128
#define NPAIR (NE*(NE-1)/2)   // 8128
#define NP4   (DD/4)          // 192 float4 per row

#define KSPLIT 16
#define KC     (DD/KSPLIT)    // 48
#define PITCH  132
#define NBLK   256

typedef unsigned long long ull;

// Scratch (no allocations allowed)
__device__ float g_emb[BB*NE*DD];          // normalized embeddings (3 MB)
__device__ float g_par[KSPLIT][BB*NE*NE];  // split-K partial sims (8 MB)
__device__ float g_cinv[BB];               // 1/(std+1e-5)
// flag protocol -- every counter returns to 0 by end of launch (replay-safe)
__device__ int g_poolcnt[BB];   // pool blocks arrived per batch   (32 -> 0)
__device__ int g_passcnt[BB];   // syrk blocks past pool-wait      (16 -> 0)
__device__ int g_simcnt[BB];    // syrk blocks done per batch      (16 -> 0)
__device__ int g_ready[BB];     // cinv ready flag                 (1  -> 0)
__device__ int g_readycnt[BB];  // cls blocks past ready-wait      (32 -> 0)

// ---- packed f32x2 helpers ------------------------------------------------
__device__ __forceinline__ void fma2(ull &d, ull a, ull b) {
    asm("fma.rn.f32x2 %0, %1, %2, %0;" : "+l"(d) : "l"(a), "l"(b));
}
__device__ __forceinline__ ull pack2(float v) {
    ull r; unsigned u = __float_as_uint(v);
    asm("mov.b64 %0, {%1, %1};" : "=l"(r) : "r"(u));
    return r;
}
__device__ __forceinline__ void unpack2(ull v, float &lo, float &hi) {
    unsigned a, b;
    asm("mov.b64 {%0, %1}, %2;" : "=r"(a), "=r"(b) : "l"(v));
    lo = __uint_as_float(a); hi = __uint_as_float(b);
}

// ---------------------------------------------------------------------------
__global__ void __launch_bounds__(256, 2)
k_all(const float* __restrict__ x,
      const int*   __restrict__ starts,
      const int*   __restrict__ lengths,
      const int*   __restrict__ hts,
      const float* __restrict__ thr,
      const float* __restrict__ W1,
      const float* __restrict__ b1,
      const float* __restrict__ W2,
      const float* __restrict__ b2,
      float*       __restrict__ out) {
    const int blk  = blockIdx.x;          // 0..255
    const int tid  = threadIdx.x;         // 256
    const int lane = tid & 31;
    const int wrp  = tid >> 5;

    __shared__ __align__(16) float At[KC][PITCH];    // syrk tile (25.3 KB)
    __shared__ float  wns[4][2];
    __shared__ float  sinv[4];
    __shared__ float  r0[128], r1[128], r2[128], r3[128];
    __shared__ int    rf[128];
    __shared__ double sS[8], sQ[8];

    // ============ Phase 1: pool 4 spans (64 threads per span) ==============
    {
        const int g   = tid >> 6;         // span group 0..3
        const int t64 = tid & 63;
        const int sp  = blk*4 + g;        // span id = b*NE + e
        const int b   = sp >> 7;
        const int s   = starts[sp];
        const int len = lengths[sp];
        const float invl = 1.0f / (float)len;
        const float4* base = (const float4*)x + ((long)b*LL + s)*NP4 + t64;

        float4 a0 = make_float4(0,0,0,0), a1 = a0, a2 = a0;
        #pragma unroll
        for (int t = 0; t < 16; ++t) {
            if (t < len) {
                const float4 v0 = base[(long)t*NP4      ];
                const float4 v1 = base[(long)t*NP4 +  64];
                const float4 v2 = base[(long)t*NP4 + 128];
                a0.x+=v0.x; a0.y+=v0.y; a0.z+=v0.z; a0.w+=v0.w;
                a1.x+=v1.x; a1.y+=v1.y; a1.z+=v1.z; a1.w+=v1.w;
                a2.x+=v2.x; a2.y+=v2.y; a2.z+=v2.z; a2.w+=v2.w;
            }
        }
        a0.x*=invl; a0.y*=invl; a0.z*=invl; a0.w*=invl;
        a1.x*=invl; a1.y*=invl; a1.z*=invl; a1.w*=invl;
        a2.x*=invl; a2.y*=invl; a2.z*=invl; a2.w*=invl;

        float ss = a0.x*a0.x+a0.y*a0.y+a0.z*a0.z+a0.w*a0.w
                 + a1.x*a1.x+a1.y*a1.y+a1.z*a1.z+a1.w*a1.w
                 + a2.x*a2.x+a2.y*a2.y+a2.z*a2.z+a2.w*a2.w;
        #pragma unroll
        for (int o = 16; o > 0; o >>= 1) ss += __shfl_xor_sync(0xffffffffu, ss, o);
        if (lane == 0) wns[g][wrp & 1] = ss;
        __syncthreads();
        if (t64 == 0) sinv[g] = 1.0f / sqrtf(wns[g][0] + wns[g][1]);
        __syncthreads();
        const float inv = sinv[g];
        float4* Eo = (float4*)g_emb + (long)sp*NP4 + t64;
        Eo[  0] = make_float4(a0.x*inv, a0.y*inv, a0.z*inv, a0.w*inv);
        Eo[ 64] = make_float4(a1.x*inv, a1.y*inv, a1.z*inv, a1.w*inv);
        Eo[128] = make_float4(a2.x*inv, a2.y*inv, a2.z*inv, a2.w*inv);
    }
    __threadfence();
    __syncthreads();
    if (tid == 0) atomicAdd(&g_poolcnt[blk >> 5], 1);   // batch of my 4 spans

    // ============ Phase 2: split-K syrk on blocks 0..127 ===================
    if (blk < 128) {
        const int b  = blk >> 4;
        const int kc = blk & 15;
        if (tid == 0) {
            while (*(volatile int*)&g_poolcnt[b] < 32) __nanosleep(32);
            const int a = atomicAdd(&g_passcnt[b], 1);
            if (a == 15) { g_passcnt[b] = 0; g_poolcnt[b] = 0; }   // last consumer resets
        }
        __syncthreads();

        const float4* Eb4 = (const float4*)g_emb + (long)b*NE*NP4 + kc*(KC/4);
        #pragma unroll
        for (int e = 0; e < 6; ++e) {
            const int idx = tid + e*256;
            const int j  = idx & 127;
            const int kg = idx >> 7;
            const float4 v = __ldcg(&Eb4[(long)j*NP4 + kg]);
            At[4*kg+0][j] = v.x;
            At[4*kg+1][j] = v.y;
            At[4*kg+2][j] = v.z;
            At[4*kg+3][j] = v.w;
        }
        __syncthreads();

        const int ty = tid >> 4, tx = tid & 15;
        const int i8 = ty*8, j8 = tx*8;
        ull c[8][4];
        #pragma unroll
        for (int r = 0; r < 8; ++r)
            #pragma unroll
            for (int q = 0; q < 4; ++q) c[r][q] = 0ull;

        #pragma unroll 4
        for (int kk = 0; kk < KC; ++kk) {
            const float4 alo = *(const float4*)&At[kk][i8];
            const float4 ahi = *(const float4*)&At[kk][i8 + 4];
            ull a2[8];
            a2[0]=pack2(alo.x); a2[1]=pack2(alo.y); a2[2]=pack2(alo.z); a2[3]=pack2(alo.w);
            a2[4]=pack2(ahi.x); a2[5]=pack2(ahi.y); a2[6]=pack2(ahi.z); a2[7]=pack2(ahi.w);
            const ulonglong2 bv0 = *(const ulonglong2*)&At[kk][j8];
            const ulonglong2 bv1 = *(const ulonglong2*)&At[kk][j8 + 4];
            ull bb[4] = {bv0.x, bv0.y, bv1.x, bv1.y};
            #pragma unroll
            for (int r = 0; r < 8; ++r)
                #pragma unroll
                for (int q = 0; q < 4; ++q) fma2(c[r][q], a2[r], bb[q]);
        }

        float* P = g_par[kc] + (long)b*NE*NE + i8*NE + j8;
        #pragma unroll
        for (int r = 0; r < 8; ++r) {
            float l0,h0,l1,h1,l2,h2,l3,h3;
            unpack2(c[r][0], l0, h0);
            unpack2(c[r][1], l1, h1);
            unpack2(c[r][2], l2, h2);
            unpack2(c[r][3], l3, h3);
            ((float4*)(P + (long)r*NE))[0] = make_float4(l0, h0, l1, h1);
            ((float4*)(P + (long)r*NE))[1] = make_float4(l2, h2, l3, h3);
        }
        __threadfence();
        __syncthreads();
        if (tid == 0) atomicAdd(&g_simcnt[b], 1);
    }
    // ============ Phase 3: stats on blocks 128..135 ========================
    else if (blk < 136) {
        const int b = blk - 128;
        if (tid == 0) {
            while (*(volatile int*)&g_simcnt[b] < 16) __nanosleep(64);
            g_simcnt[b] = 0;                              // single consumer resets
        }
        __syncthreads();

        float s = 0.f, q = 0.f;
        #pragma unroll 4
        for (int it = 0; it < 16; ++it) {
            const int f = tid + it*256;
            float4 acc = make_float4(0.f,0.f,0.f,0.f);
            #pragma unroll
            for (int kc = 0; kc < KSPLIT; ++kc) {
                const float4 v = __ldcg(&((const float4*)(g_par[kc] + (long)b*NE*NE))[f]);
                acc.x+=v.x; acc.y+=v.y; acc.z+=v.z; acc.w+=v.w;
            }
            s += acc.x + acc.y + acc.z + acc.w;
            q += acc.x*acc.x + acc.y*acc.y + acc.z*acc.z + acc.w*acc.w;
        }
        double ds = (double)s, dq = (double)q;
        #pragma unroll
        for (int o = 16; o > 0; o >>= 1) {
            ds += __shfl_xor_sync(0xffffffffu, ds, o);
            dq += __shfl_xor_sync(0xffffffffu, dq, o);
        }
        if (lane == 0) { sS[wrp] = ds; sQ[wrp] = dq; }
        __syncthreads();
        if (tid == 0) {
            double ts = 0.0, tq = 0.0;
            #pragma unroll
            for (int w = 0; w < 8; ++w) { ts += sS[w]; tq += sQ[w]; }
            const double n  = (double)(NE*NE);
            const double sd = sqrt((tq - ts*ts/n) / (n - 1.0));
            g_cinv[b] = 1.0f / ((float)sd + 1e-5f);
            __threadfence();
            *(volatile int*)&g_ready[b] = 1;
        }
    }

    // ============ Phase 4: MLP collapse (per-block, no sync needed) ========
    if (tid < 128) {
        const float w1  = W1[tid];
        const float w20 = W2[2*tid], w21 = W2[2*tid+1];
        r0[tid] = (w1 > 0.f) ? w1*w20 : 0.f;
        r1[tid] = (w1 > 0.f) ? w1*w21 : 0.f;
        r2[tid] = (w1 < 0.f) ? w1*w20 : 0.f;
        r3[tid] = (w1 < 0.f) ? w1*w21 : 0.f;
        rf[tid] = (b1[tid] != 0.f) ? 1 : 0;
    }
    __syncthreads();
    #pragma unroll
    for (int o = 64; o > 0; o >>= 1) {
        if (tid < o) {
            r0[tid]+=r0[tid+o]; r1[tid]+=r1[tid+o];
            r2[tid]+=r2[tid+o]; r3[tid]+=r3[tid+o];
            rf[tid]|=rf[tid+o];
        }
        __syncthreads();
    }

    // ============ Phase 5: classify 254 pairs of batch blk>>5 ==============
    {
        const int b = blk >> 5;
        if (tid == 0) {
            while (*(volatile int*)&g_ready[b] == 0) __nanosleep(64);
            const int a = atomicAdd(&g_readycnt[b], 1);
            if (a == 31) { g_readycnt[b] = 0; g_ready[b] = 0; }   // last consumer resets
        }
        __syncthreads();

        if (tid < 254) {
            const int gp = b*NPAIR + (blk & 31)*254 + tid;
            const int2 ht = ((const int2*)hts)[gp];
            const long off = (long)b*NE*NE + ht.x*NE + ht.y;
            float s16 = 0.f;
            #pragma unroll
            for (int kc = 0; kc < KSPLIT; ++kc) s16 += __ldcg(&g_par[kc][off]);

            const float cinv = __ldcg(&g_cinv[b]);
            const float pv   = (s16 - __ldg(thr)) * cinv;
            const float b20  = __ldg(&b2[0]), b21 = __ldg(&b2[1]);

            float o0, o1;
            if (rf[0] == 0) {
                o0 = fmaf(pv, (pv > 0.f) ? r0[0] : r2[0], b20);
                o1 = fmaf(pv, (pv > 0.f) ? r1[0] : r3[0], b21);
            } else {
                o0 = b20; o1 = b21;
                #pragma unroll 8
                for (int k = 0; k < 128; ++k) {
                    const float h = fmaxf(fmaf(pv, __ldg(&W1[k]), __ldg(&b1[k])), 0.f);
                    o0 = fmaf(h, __ldg(&W2[2*k  ]), o0);
                    o1 = fmaf(h, __ldg(&W2[2*k+1]), o1);
                }
            }
            ((float2*)out)[gp] = make_float2(o0, o1);
        }
    }
}

// ---------------------------------------------------------------------------
extern "C" void kernel_launch(void* const* d_in, const int* in_sizes, int n_in,
                              void* d_out, int out_size) {
    const float* x       = (const float*)d_in[0];
    const int*   starts  = (const int*)  d_in[1];
    const int*   lengths = (const int*)  d_in[2];
    const int*   hts     = (const int*)  d_in[3];
    const float* thr     = (const float*)d_in[4];
    const float* W1      = (const float*)d_in[5];
    const float* b1      = (const float*)d_in[6];
    const float* W2      = (const float*)d_in[7];
    const float* b2      = (const float*)d_in[8];
    float* out = (float*)d_out;

    k_all<<<NBLK, 256>>>(x, starts, lengths, hts, thr, W1, b1, W2, b2, out);
}

// round 9
// speedup vs baseline: 2.1033x; 1.0022x over previous
#include <cuda_runtime.h>
#include <math.h>

#define BB 8
#define LL 8192
#define DD 768
#define NE 128
#define NPAIR (NE*(NE-1)/2)   // 8128
#define NP4   (DD/4)          // 192 float4 per row

#define KSPLIT 16
#define KC     (DD/KSPLIT)    // 48
#define PITCH  132
#define NBLK   256
#define NTILE  136            // upper-triangular 8x8 tiles of 16x16 grid

typedef unsigned long long ull;

// Scratch (no allocations allowed)
__device__ float g_emb[BB*NE*DD];          // normalized embeddings (3 MB)
__device__ float g_par[KSPLIT][BB*NE*NE];  // split-K partials (upper tiles only)
__device__ float g_sim[BB*NE*NE];          // summed sims (written by stats)
__device__ float g_cinv[BB];               // 1/(std+1e-5)
// flag protocol -- every counter returns to 0 by end of launch (replay-safe)
__device__ int g_poolcnt[BB];   // pool blocks arrived per batch   (32 -> 0)
__device__ int g_passcnt[BB];   // syrk blocks past pool-wait      (16 -> 0)
__device__ int g_simcnt[BB];    // syrk blocks done per batch      (16 -> 0)
__device__ int g_ready[BB];     // cinv+sims ready flag            (1  -> 0)
__device__ int g_readycnt[BB];  // cls blocks past ready-wait      (32 -> 0)

// ---- release/acquire primitives (no per-thread membar needed) -------------
__device__ __forceinline__ void red_add_release(int* p, int v) {
    asm volatile("red.release.gpu.global.add.s32 [%0], %1;"
                 :: "l"(p), "r"(v) : "memory");
}
__device__ __forceinline__ int atom_add_release(int* p, int v) {
    int r;
    asm volatile("atom.release.gpu.global.add.s32 %0, [%1], %2;"
                 : "=r"(r) : "l"(p), "r"(v) : "memory");
    return r;
}
__device__ __forceinline__ int ld_acquire(const int* p) {
    int r;
    asm volatile("ld.acquire.gpu.global.s32 %0, [%1];"
                 : "=r"(r) : "l"(p) : "memory");
    return r;
}
__device__ __forceinline__ void st_release(int* p, int v) {
    asm volatile("st.release.gpu.global.s32 [%0], %1;"
                 :: "l"(p), "r"(v) : "memory");
}

// ---- packed f32x2 helpers ------------------------------------------------
__device__ __forceinline__ void fma2(ull &d, ull a, ull b) {
    asm("fma.rn.f32x2 %0, %1, %2, %0;" : "+l"(d) : "l"(a), "l"(b));
}
__device__ __forceinline__ ull pack2(float v) {
    ull r; unsigned u = __float_as_uint(v);
    asm("mov.b64 %0, {%1, %1};" : "=l"(r) : "r"(u));
    return r;
}
__device__ __forceinline__ void unpack2(ull v, float &lo, float &hi) {
    unsigned a, b;
    asm("mov.b64 {%0, %1}, %2;" : "=r"(a), "=r"(b) : "l"(v));
    lo = __uint_as_float(a); hi = __uint_as_float(b);
}

// ---------------------------------------------------------------------------
__global__ void __launch_bounds__(256, 2)
k_all(const float* __restrict__ x,
      const int*   __restrict__ starts,
      const int*   __restrict__ lengths,
      const int*   __restrict__ hts,
      const float* __restrict__ thr,
      const float* __restrict__ W1,
      const float* __restrict__ b1,
      const float* __restrict__ W2,
      const float* __restrict__ b2,
      float*       __restrict__ out) {
    const int blk  = blockIdx.x;          // 0..255
    const int tid  = threadIdx.x;         // 256
    const int lane = tid & 31;
    const int wrp  = tid >> 5;

    __shared__ __align__(16) float At[KC][PITCH];    // syrk tile (25.3 KB)
    __shared__ float  wns[4][2];
    __shared__ float  sinv[4];
    __shared__ float  r0[128], r1[128], r2[128], r3[128];
    __shared__ int    rf[128];
    __shared__ double sS[8], sQ[8];

    // ============ Phase 1: pool 4 spans (64 threads per span) ==============
    {
        const int g   = tid >> 6;         // span group 0..3
        const int t64 = tid & 63;
        const int sp  = blk*4 + g;        // span id = b*NE + e
        const int b   = sp >> 7;
        const int s   = starts[sp];
        const int len = lengths[sp];
        const float invl = 1.0f / (float)len;
        const float4* base = (const float4*)x + ((long)b*LL + s)*NP4 + t64;

        float4 a0 = make_float4(0,0,0,0), a1 = a0, a2 = a0;
        #pragma unroll
        for (int t = 0; t < 16; ++t) {
            if (t < len) {
                const float4 v0 = base[(long)t*NP4      ];
                const float4 v1 = base[(long)t*NP4 +  64];
                const float4 v2 = base[(long)t*NP4 + 128];
                a0.x+=v0.x; a0.y+=v0.y; a0.z+=v0.z; a0.w+=v0.w;
                a1.x+=v1.x; a1.y+=v1.y; a1.z+=v1.z; a1.w+=v1.w;
                a2.x+=v2.x; a2.y+=v2.y; a2.z+=v2.z; a2.w+=v2.w;
            }
        }
        a0.x*=invl; a0.y*=invl; a0.z*=invl; a0.w*=invl;
        a1.x*=invl; a1.y*=invl; a1.z*=invl; a1.w*=invl;
        a2.x*=invl; a2.y*=invl; a2.z*=invl; a2.w*=invl;

        float ss = a0.x*a0.x+a0.y*a0.y+a0.z*a0.z+a0.w*a0.w
                 + a1.x*a1.x+a1.y*a1.y+a1.z*a1.z+a1.w*a1.w
                 + a2.x*a2.x+a2.y*a2.y+a2.z*a2.z+a2.w*a2.w;
        #pragma unroll
        for (int o = 16; o > 0; o >>= 1) ss += __shfl_xor_sync(0xffffffffu, ss, o);
        if (lane == 0) wns[g][wrp & 1] = ss;
        __syncthreads();
        if (t64 == 0) sinv[g] = 1.0f / sqrtf(wns[g][0] + wns[g][1]);
        __syncthreads();
        const float inv = sinv[g];
        float4* Eo = (float4*)g_emb + (long)sp*NP4 + t64;
        __stcg(&Eo[  0], make_float4(a0.x*inv, a0.y*inv, a0.z*inv, a0.w*inv));
        __stcg(&Eo[ 64], make_float4(a1.x*inv, a1.y*inv, a1.z*inv, a1.w*inv));
        __stcg(&Eo[128], make_float4(a2.x*inv, a2.y*inv, a2.z*inv, a2.w*inv));
    }
    __syncthreads();
    if (tid == 0) red_add_release(&g_poolcnt[blk >> 5], 1);

    // ============ Phase 2: symmetric split-K syrk on blocks 0..127 =========
    if (blk < 128) {
        const int b  = blk >> 4;
        const int kc = blk & 15;
        if (tid == 0) {
            while (ld_acquire(&g_poolcnt[b]) < 32) __nanosleep(32);
            const int a = atom_add_release(&g_passcnt[b], 1);
            if (a == 15) { g_passcnt[b] = 0; g_poolcnt[b] = 0; }  // last consumer resets
        }
        __syncthreads();

        const float4* Eb4 = (const float4*)g_emb + (long)b*NE*NP4 + kc*(KC/4);
        #pragma unroll
        for (int e = 0; e < 6; ++e) {
            const int idx = tid + e*256;
            const int j  = idx & 127;
            const int kg = idx >> 7;
            const float4 v = __ldcg(&Eb4[(long)j*NP4 + kg]);
            At[4*kg+0][j] = v.x;
            At[4*kg+1][j] = v.y;
            At[4*kg+2][j] = v.z;
            At[4*kg+3][j] = v.w;
        }
        __syncthreads();

        if (tid < NTILE) {
            // warp-compact upper-triangular tile map: tid -> (ty,tx), tx>=ty
            const int tp = 135 - tid;
            const int m  = (int)((sqrtf((float)(8*tp + 1)) - 1.0f) * 0.5f);
            const int ty = 15 - m;
            const int tx = 15 - (tp - (m*(m+1)) / 2);
            const int i8 = ty*8, j8 = tx*8;

            ull c[8][4];
            #pragma unroll
            for (int r = 0; r < 8; ++r)
                #pragma unroll
                for (int q = 0; q < 4; ++q) c[r][q] = 0ull;

            #pragma unroll 4
            for (int kk = 0; kk < KC; ++kk) {
                const float4 alo = *(const float4*)&At[kk][i8];
                const float4 ahi = *(const float4*)&At[kk][i8 + 4];
                ull a2[8];
                a2[0]=pack2(alo.x); a2[1]=pack2(alo.y); a2[2]=pack2(alo.z); a2[3]=pack2(alo.w);
                a2[4]=pack2(ahi.x); a2[5]=pack2(ahi.y); a2[6]=pack2(ahi.z); a2[7]=pack2(ahi.w);
                const ulonglong2 bv0 = *(const ulonglong2*)&At[kk][j8];
                const ulonglong2 bv1 = *(const ulonglong2*)&At[kk][j8 + 4];
                ull bb[4] = {bv0.x, bv0.y, bv1.x, bv1.y};
                #pragma unroll
                for (int r = 0; r < 8; ++r)
                    #pragma unroll
                    for (int q = 0; q < 4; ++q) fma2(c[r][q], a2[r], bb[q]);
            }

            float* P = g_par[kc] + (long)b*NE*NE + i8*NE + j8;
            #pragma unroll
            for (int r = 0; r < 8; ++r) {
                float l0,h0,l1,h1,l2,h2,l3,h3;
                unpack2(c[r][0], l0, h0);
                unpack2(c[r][1], l1, h1);
                unpack2(c[r][2], l2, h2);
                unpack2(c[r][3], l3, h3);
                __stcg(&((float4*)(P + (long)r*NE))[0], make_float4(l0, h0, l1, h1));
                __stcg(&((float4*)(P + (long)r*NE))[1], make_float4(l2, h2, l3, h3));
            }
        }
        __syncthreads();
        if (tid == 0) red_add_release(&g_simcnt[b], 1);
    }
    // ============ Phase 3: stats + sim-sum on blocks 128..135 ==============
    else if (blk < 136) {
        const int b = blk - 128;
        if (tid == 0) {
            while (ld_acquire(&g_simcnt[b]) < 16) __nanosleep(64);
            g_simcnt[b] = 0;                              // single consumer resets
        }
        __syncthreads();

        float4* Ssum = (float4*)(g_sim + (long)b*NE*NE);
        float s = 0.f, q = 0.f;
        #pragma unroll 4
        for (int it = 0; it < 16; ++it) {
            const int f = tid + it*256;   // float4 index: row i = f>>5, cols 4*(f&31)..
            const int i  = f >> 5;
            const int j0 = (f & 31) * 4;
            float4 acc = make_float4(0.f,0.f,0.f,0.f);
            #pragma unroll
            for (int kc = 0; kc < KSPLIT; ++kc) {
                const float4 v = __ldcg(&((const float4*)(g_par[kc] + (long)b*NE*NE))[f]);
                acc.x+=v.x; acc.y+=v.y; acc.z+=v.z; acc.w+=v.w;
            }
            __stcg(&Ssum[f], acc);        // lower-triangle values are unused garbage
            // weights: strict upper counts twice (mirror), diagonal once, lower zero
            const float wx = (j0   > i) ? 2.f : (j0   == i) ? 1.f : 0.f;
            const float wy = (j0+1 > i) ? 2.f : (j0+1 == i) ? 1.f : 0.f;
            const float wz = (j0+2 > i) ? 2.f : (j0+2 == i) ? 1.f : 0.f;
            const float ww = (j0+3 > i) ? 2.f : (j0+3 == i) ? 1.f : 0.f;
            s += wx*acc.x + wy*acc.y + wz*acc.z + ww*acc.w;
            q += wx*acc.x*acc.x + wy*acc.y*acc.y + wz*acc.z*acc.z + ww*acc.w*acc.w;
        }
        double ds = (double)s, dq = (double)q;
        #pragma unroll
        for (int o = 16; o > 0; o >>= 1) {
            ds += __shfl_xor_sync(0xffffffffu, ds, o);
            dq += __shfl_xor_sync(0xffffffffu, dq, o);
        }
        if (lane == 0) { sS[wrp] = ds; sQ[wrp] = dq; }
        __syncthreads();
        if (tid == 0) {
            double ts = 0.0, tq = 0.0;
            #pragma unroll
            for (int w = 0; w < 8; ++w) { ts += sS[w]; tq += sQ[w]; }
            const double n  = (double)(NE*NE);
            const double sd = sqrt((tq - ts*ts/n) / (n - 1.0));
            g_cinv[b] = 1.0f / ((float)sd + 1e-5f);
        }
        __syncthreads();                  // all g_sim writes + cinv done
        if (tid == 0) st_release(&g_ready[b], 1);
    }

    // ============ Phase 4: MLP collapse (per-block, input-only) ============
    if (tid < 128) {
        const float w1  = W1[tid];
        const float w20 = W2[2*tid], w21 = W2[2*tid+1];
        r0[tid] = (w1 > 0.f) ? w1*w20 : 0.f;
        r1[tid] = (w1 > 0.f) ? w1*w21 : 0.f;
        r2[tid] = (w1 < 0.f) ? w1*w20 : 0.f;
        r3[tid] = (w1 < 0.f) ? w1*w21 : 0.f;
        rf[tid] = (b1[tid] != 0.f) ? 1 : 0;
    }
    __syncthreads();
    #pragma unroll
    for (int o = 64; o > 0; o >>= 1) {
        if (tid < o) {
            r0[tid]+=r0[tid+o]; r1[tid]+=r1[tid+o];
            r2[tid]+=r2[tid+o]; r3[tid]+=r3[tid+o];
            rf[tid]|=rf[tid+o];
        }
        __syncthreads();
    }

    // ============ Phase 5: classify 254 pairs of batch blk>>5 ==============
    {
        const int b = blk >> 5;
        if (tid == 0) {
            while (ld_acquire(&g_ready[b]) == 0) __nanosleep(64);
            const int a = atom_add_release(&g_readycnt[b], 1);
            if (a == 31) { g_readycnt[b] = 0; g_ready[b] = 0; }   // last consumer resets
        }
        __syncthreads();

        if (tid < 254) {
            const int gp = b*NPAIR + (blk & 31)*254 + tid;
            const int2 ht = ((const int2*)hts)[gp];
            const float sim = __ldcg(&g_sim[(long)b*NE*NE + ht.x*NE + ht.y]);
            const float cinv = __ldcg(&g_cinv[b]);
            const float pv   = (sim - __ldg(thr)) * cinv;
            const float b20  = __ldg(&b2[0]), b21 = __ldg(&b2[1]);

            float o0, o1;
            if (rf[0] == 0) {
                o0 = fmaf(pv, (pv > 0.f) ? r0[0] : r2[0], b20);
                o1 = fmaf(pv, (pv > 0.f) ? r1[0] : r3[0], b21);
            } else {
                o0 = b20; o1 = b21;
                #pragma unroll 8
                for (int k = 0; k < 128; ++k) {
                    const float h = fmaxf(fmaf(pv, __ldg(&W1[k]), __ldg(&b1[k])), 0.f);
                    o0 = fmaf(h, __ldg(&W2[2*k  ]), o0);
                    o1 = fmaf(h, __ldg(&W2[2*k+1]), o1);
                }
            }
            ((float2*)out)[gp] = make_float2(o0, o1);
        }
    }
}

// ---------------------------------------------------------------------------
extern "C" void kernel_launch(void* const* d_in, const int* in_sizes, int n_in,
                              void* d_out, int out_size) {
    const float* x       = (const float*)d_in[0];
    const int*   starts  = (const int*)  d_in[1];
    const int*   lengths = (const int*)  d_in[2];
    const int*   hts     = (const int*)  d_in[3];
    const float* thr     = (const float*)d_in[4];
    const float* W1      = (const float*)d_in[5];
    const float* b1      = (const float*)d_in[6];
    const float* W2      = (const float*)d_in[7];
    const float* b2      = (const float*)d_in[8];
    float* out = (float*)d_out;

    k_all<<<NBLK, 256>>>(x, starts, lengths, hts, thr, W1, b1, W2, b2, out);
}

// round 10
// speedup vs baseline: 2.2039x; 1.0478x over previous
#include <cuda_runtime.h>
#include <math.h>

#define BB 8
#define LL 8192
#define DD 768
#define NE 128
#define NPAIR (NE*(NE-1)/2)   // 8128 = 16*508
#define NP4   (DD/4)          // 192
#define KSPLIT 16
#define KC     (DD/KSPLIT)    // 48 floats per chunk
#define KC4    (KC/4)         // 12 f4 per chunk
#define PITCH  132
#define NTILE  136

typedef unsigned long long ull;

// Scratch (no allocations allowed)
__device__ float  g_par[KSPLIT][BB*NE*NE]; // raw gram partials (upper tiles)
__device__ float  g_sim[BB*NE*NE];         // cosine sims (upper region valid)
__device__ float  g_rinv[BB][NE];          // 1/||emb_i||
__device__ double g_qs[BB][4][2];          // per-quarter fp64 {sum, sumsq}
__device__ float  g_cinv[BB];              // 1/(std+1e-5)
// counters: all return to 0 every launch (replay-safe)
__device__ int g_simcnt[BB];  // syrk arrivals (16)
__device__ int g_rdyq[BB];    // quarter rinv arrivals (4)
__device__ int g_rdyq2[BB];   // quarter pass-2 (4) -> resets rdyq,rdyq2,simcnt
__device__ int g_scnt[BB];    // stats arrivals (4) -> last computes cinv
__device__ int g_ready[BB];   // cinv+sim ready (1)
__device__ int g_rcnt[BB];    // cls arrivals (16) -> resets ready,rcnt

// ---- acq/rel primitives ---------------------------------------------------
__device__ __forceinline__ void red_add_release(int* p, int v) {
    asm volatile("red.release.gpu.global.add.s32 [%0], %1;"
                 :: "l"(p), "r"(v) : "memory");
}
__device__ __forceinline__ int atom_add_acqrel(int* p, int v) {
    int r;
    asm volatile("atom.acq_rel.gpu.global.add.s32 %0, [%1], %2;"
                 : "=r"(r) : "l"(p), "r"(v) : "memory");
    return r;
}
__device__ __forceinline__ int ld_acquire(const int* p) {
    int r;
    asm volatile("ld.acquire.gpu.global.s32 %0, [%1];"
                 : "=r"(r) : "l"(p) : "memory");
    return r;
}
__device__ __forceinline__ void st_release(int* p, int v) {
    asm volatile("st.release.gpu.global.s32 [%0], %1;"
                 :: "l"(p), "r"(v) : "memory");
}

// ---- packed f32x2 helpers ------------------------------------------------
__device__ __forceinline__ void fma2(ull &d, ull a, ull b) {
    asm("fma.rn.f32x2 %0, %1, %2, %0;" : "+l"(d) : "l"(a), "l"(b));
}
__device__ __forceinline__ ull pack2(float v) {
    ull r; unsigned u = __float_as_uint(v);
    asm("mov.b64 %0, {%1, %1};" : "=l"(r) : "r"(u));
    return r;
}
__device__ __forceinline__ void unpack2(ull v, float &lo, float &hi) {
    unsigned a, b;
    asm("mov.b64 {%0, %1}, %2;" : "=r"(a), "=r"(b) : "l"(v));
    lo = __uint_as_float(a); hi = __uint_as_float(b);
}

// ---------------------------------------------------------------------------
__global__ void __launch_bounds__(256)
k_all(const float* __restrict__ x,
      const int*   __restrict__ starts,
      const int*   __restrict__ lengths,
      const int*   __restrict__ hts,
      const float* __restrict__ thr,
      const float* __restrict__ W1,
      const float* __restrict__ b1,
      const float* __restrict__ W2,
      const float* __restrict__ b2,
      float*       __restrict__ out) {
    const int blk  = blockIdx.x;          // 0..127
    const int b    = blk >> 4;            // batch
    const int kc   = blk & 15;            // k-chunk
    const int tid  = threadIdx.x;         // 256

    __shared__ __align__(16) float At[KC][PITCH];   // pooled k-slice [k][span]
    __shared__ int   sSt[NE], sLn[NE];
    __shared__ float sRi[NE];
    __shared__ float r0[128], r1[128], r2[128], r3[128];
    __shared__ int   rf[128];
    __shared__ double sS8[8], sQ8[8];

    // ======= Phase A: gather-pool this block's 48-float slice of 128 spans =
    if (tid < NE) {
        sSt[tid] = starts[b*NE + tid];
        sLn[tid] = lengths[b*NE + tid];
    }
    __syncthreads();

    {
        const int grp = tid >> 4;         // 0..15 (span group within pass)
        const int c   = tid & 15;         // f4 slot (0..11 active)
        const float4* xb4 = (const float4*)x + (long)b*LL*NP4 + kc*KC4 + c;

        #pragma unroll
        for (int pass = 0; pass < 8; pass += 2) {
            const int sp0 = pass*16 + grp;
            const int sp1 = sp0 + 16;
            if (c < 12) {
                const int s0 = sSt[sp0], l0 = sLn[sp0];
                const int s1 = sSt[sp1], l1 = sLn[sp1];
                const float4* p0 = xb4 + (long)s0*NP4;
                const float4* p1 = xb4 + (long)s1*NP4;
                float4 a0 = make_float4(0,0,0,0), a1 = a0;
                #pragma unroll
                for (int t = 0; t < 16; ++t) {
                    if (t < l0) { const float4 v = p0[(long)t*NP4]; a0.x+=v.x; a0.y+=v.y; a0.z+=v.z; a0.w+=v.w; }
                    if (t < l1) { const float4 v = p1[(long)t*NP4]; a1.x+=v.x; a1.y+=v.y; a1.z+=v.z; a1.w+=v.w; }
                }
                const float i0 = 1.0f / (float)l0;
                const float i1 = 1.0f / (float)l1;
                At[4*c+0][sp0] = a0.x*i0;  At[4*c+0][sp1] = a1.x*i1;
                At[4*c+1][sp0] = a0.y*i0;  At[4*c+1][sp1] = a1.y*i1;
                At[4*c+2][sp0] = a0.z*i0;  At[4*c+2][sp1] = a1.z*i1;
                At[4*c+3][sp0] = a0.w*i0;  At[4*c+3][sp1] = a1.w*i1;
            }
        }
    }
    __syncthreads();

    // ======= Phase B: upper-triangular FFMA2 syrk on the slice =============
    if (tid < NTILE) {
        const int tp = 135 - tid;
        const int m  = (int)((sqrtf((float)(8*tp + 1)) - 1.0f) * 0.5f);
        const int ty = 15 - m;
        const int tx = 15 - (tp - (m*(m+1)) / 2);
        const int i8 = ty*8, j8 = tx*8;

        ull c[8][4];
        #pragma unroll
        for (int r = 0; r < 8; ++r)
            #pragma unroll
            for (int q = 0; q < 4; ++q) c[r][q] = 0ull;

        #pragma unroll 4
        for (int kk = 0; kk < KC; ++kk) {
            const float4 alo = *(const float4*)&At[kk][i8];
            const float4 ahi = *(const float4*)&At[kk][i8 + 4];
            ull a2[8];
            a2[0]=pack2(alo.x); a2[1]=pack2(alo.y); a2[2]=pack2(alo.z); a2[3]=pack2(alo.w);
            a2[4]=pack2(ahi.x); a2[5]=pack2(ahi.y); a2[6]=pack2(ahi.z); a2[7]=pack2(ahi.w);
            const ulonglong2 bv0 = *(const ulonglong2*)&At[kk][j8];
            const ulonglong2 bv1 = *(const ulonglong2*)&At[kk][j8 + 4];
            ull bb[4] = {bv0.x, bv0.y, bv1.x, bv1.y};
            #pragma unroll
            for (int r = 0; r < 8; ++r)
                #pragma unroll
                for (int q = 0; q < 4; ++q) fma2(c[r][q], a2[r], bb[q]);
        }

        float* P = g_par[kc] + (long)b*NE*NE + i8*NE + j8;
        #pragma unroll
        for (int r = 0; r < 8; ++r) {
            float l0,h0,l1,h1,l2,h2,l3,h3;
            unpack2(c[r][0], l0, h0);
            unpack2(c[r][1], l1, h1);
            unpack2(c[r][2], l2, h2);
            unpack2(c[r][3], l3, h3);
            __stcg(&((float4*)(P + (long)r*NE))[0], make_float4(l0, h0, l1, h1));
            __stcg(&((float4*)(P + (long)r*NE))[1], make_float4(l2, h2, l3, h3));
        }
    }
    __syncthreads();
    if (tid == 0) red_add_release(&g_simcnt[b], 1);

    // ======= Phase C: quarter stats on kc<4 ================================
    if (kc < 4) {
        const int q = kc;                 // quarter = rows [q*32, q*32+32)
        if (tid == 0) {
            while (ld_acquire(&g_simcnt[b]) < 16) __nanosleep(32);
        }
        __syncthreads();

        // sum 16 partial planes for this quarter (held in registers)
        float4 acc[4];
        #pragma unroll
        for (int it = 0; it < 4; ++it) {
            const int f = q*1024 + tid + it*256;
            float4 a = make_float4(0.f,0.f,0.f,0.f);
            #pragma unroll
            for (int k2 = 0; k2 < KSPLIT; ++k2) {
                const float4 v = __ldcg(&((const float4*)(g_par[k2] + (long)b*NE*NE))[f]);
                a.x+=v.x; a.y+=v.y; a.z+=v.z; a.w+=v.w;
            }
            acc[it] = a;
            // diagonal -> rinv
            const int i  = f >> 5;
            const int j0 = (f & 31) * 4;
            if (i >= j0 && i < j0 + 4) {
                const float d = (i == j0) ? a.x : (i == j0+1) ? a.y : (i == j0+2) ? a.z : a.w;
                __stcg(&g_rinv[b][i], rsqrtf(fmaxf(d, 1e-16f)));
            }
        }
        __syncthreads();
        if (tid == 0) {
            red_add_release(&g_rdyq[b], 1);
            while (ld_acquire(&g_rdyq[b]) < 4) __nanosleep(32);
            const int a2 = atom_add_acqrel(&g_rdyq2[b], 1);
            if (a2 == 3) { g_rdyq[b] = 0; g_rdyq2[b] = 0; g_simcnt[b] = 0; }
        }
        __syncthreads();

        // stage all 128 rinv in smem
        if (tid < NE) sRi[tid] = __ldcg(&g_rinv[b][tid]);
        __syncthreads();

        // normalize, write sim, accumulate weighted stats
        float s = 0.f, qq = 0.f;
        #pragma unroll
        for (int it = 0; it < 4; ++it) {
            const int f  = q*1024 + tid + it*256;
            const int i  = f >> 5;
            const int j0 = (f & 31) * 4;
            const float ri = sRi[i];
            float4 v = acc[it];
            v.x *= ri * sRi[j0  ];
            v.y *= ri * sRi[j0+1];
            v.z *= ri * sRi[j0+2];
            v.w *= ri * sRi[j0+3];
            __stcg(&((float4*)(g_sim + (long)b*NE*NE))[f], v);
            const float wx = (j0   > i) ? 2.f : (j0   == i) ? 1.f : 0.f;
            const float wy = (j0+1 > i) ? 2.f : (j0+1 == i) ? 1.f : 0.f;
            const float wz = (j0+2 > i) ? 2.f : (j0+2 == i) ? 1.f : 0.f;
            const float ww = (j0+3 > i) ? 2.f : (j0+3 == i) ? 1.f : 0.f;
            s  += wx*v.x + wy*v.y + wz*v.z + ww*v.w;
            qq += wx*v.x*v.x + wy*v.y*v.y + wz*v.z*v.z + ww*v.w*v.w;
        }
        double ds = (double)s, dq = (double)qq;
        #pragma unroll
        for (int o = 16; o > 0; o >>= 1) {
            ds += __shfl_xor_sync(0xffffffffu, ds, o);
            dq += __shfl_xor_sync(0xffffffffu, dq, o);
        }
        if ((tid & 31) == 0) { sS8[tid >> 5] = ds; sQ8[tid >> 5] = dq; }
        __syncthreads();
        if (tid == 0) {
            double ts = 0.0, tq = 0.0;
            #pragma unroll
            for (int w = 0; w < 8; ++w) { ts += sS8[w]; tq += sQ8[w]; }
            g_qs[b][q][0] = ts;
            g_qs[b][q][1] = tq;
            const int a3 = atom_add_acqrel(&g_scnt[b], 1);
            if (a3 == 3) {                // last quarter: deterministic combine
                double fs = 0.0, fq = 0.0;
                #pragma unroll
                for (int q2 = 0; q2 < 4; ++q2) {
                    fs += g_qs[b][q2][0];
                    fq += g_qs[b][q2][1];
                }
                const double n  = (double)(NE*NE);
                const double sd = sqrt((fq - fs*fs/n) / (n - 1.0));
                g_cinv[b] = 1.0f / ((float)sd + 1e-5f);
                g_scnt[b] = 0;
                st_release(&g_ready[b], 1);
            }
        }
    }

    // ======= Phase D: MLP collapse (input-only, per block) =================
    if (tid < 128) {
        const float w1  = W1[tid];
        const float w20 = W2[2*tid], w21 = W2[2*tid+1];
        r0[tid] = (w1 > 0.f) ? w1*w20 : 0.f;
        r1[tid] = (w1 > 0.f) ? w1*w21 : 0.f;
        r2[tid] = (w1 < 0.f) ? w1*w20 : 0.f;
        r3[tid] = (w1 < 0.f) ? w1*w21 : 0.f;
        rf[tid] = (b1[tid] != 0.f) ? 1 : 0;
    }
    __syncthreads();
    #pragma unroll
    for (int o = 64; o > 0; o >>= 1) {
        if (tid < o) {
            r0[tid]+=r0[tid+o]; r1[tid]+=r1[tid+o];
            r2[tid]+=r2[tid+o]; r3[tid]+=r3[tid+o];
            rf[tid]|=rf[tid+o];
        }
        __syncthreads();
    }

    // ======= Phase E: classify 508 pairs of batch b ========================
    {
        if (tid == 0) {
            while (ld_acquire(&g_ready[b]) == 0) __nanosleep(64);
            const int a = atom_add_acqrel(&g_rcnt[b], 1);
            if (a == 15) { g_rcnt[b] = 0; g_ready[b] = 0; }
        }
        __syncthreads();

        const float cinv = __ldcg(&g_cinv[b]);
        const float t0   = __ldg(thr);
        const float b20  = __ldg(&b2[0]), b21 = __ldg(&b2[1]);
        const float* Sb  = g_sim + (long)b*NE*NE;

        #pragma unroll
        for (int it = 0; it < 2; ++it) {
            const int lp = kc*508 + tid + it*256;
            if (lp < (kc+1)*508 && (tid + it*256) < 508) {
                const int gp = b*NPAIR + lp;
                const int2 ht = ((const int2*)hts)[gp];
                const float sim = __ldcg(&Sb[ht.x*NE + ht.y]);
                const float pv  = (sim - t0) * cinv;
                float o0, o1;
                if (rf[0] == 0) {
                    o0 = fmaf(pv, (pv > 0.f) ? r0[0] : r2[0], b20);
                    o1 = fmaf(pv, (pv > 0.f) ? r1[0] : r3[0], b21);
                } else {
                    o0 = b20; o1 = b21;
                    #pragma unroll 8
                    for (int k = 0; k < 128; ++k) {
                        const float h = fmaxf(fmaf(pv, __ldg(&W1[k]), __ldg(&b1[k])), 0.f);
                        o0 = fmaf(h, __ldg(&W2[2*k  ]), o0);
                        o1 = fmaf(h, __ldg(&W2[2*k+1]), o1);
                    }
                }
                ((float2*)out)[gp] = make_float2(o0, o1);
            }
        }
    }
}

// ---------------------------------------------------------------------------
extern "C" void kernel_launch(void* const* d_in, const int* in_sizes, int n_in,
                              void* d_out, int out_size) {
    const float* x       = (const float*)d_in[0];
    const int*   starts  = (const int*)  d_in[1];
    const int*   lengths = (const int*)  d_in[2];
    const int*   hts     = (const int*)  d_in[3];
    const float* thr     = (const float*)d_in[4];
    const float* W1      = (const float*)d_in[5];
    const float* b1      = (const float*)d_in[6];
    const float* W2      = (const float*)d_in[7];
    const float* b2      = (const float*)d_in[8];
    float* out = (float*)d_out;

    k_all<<<BB*KSPLIT, 256>>>(x, starts, lengths, hts, thr, W1, b1, W2, b2, out);
}

// round 11
// speedup vs baseline: 2.2605x; 1.0257x over previous
#include <cuda_runtime.h>
#include <math.h>

#define BB 8
#define LL 8192
#define DD 768
#define NE 128
#define NPAIR (NE*(NE-1)/2)   // 8128
#define NP4   (DD/4)          // 192
#define KSPLIT 16
#define KC     (DD/KSPLIT)    // 48
#define KC4    (KC/4)         // 12
#define PITCH  132
#define NTILE  136
#define TPB    512

typedef unsigned long long ull;

// quarter pair ranges (triu row-major): rows [32q,32q+32)
__device__ __constant__ int c_qoff[5] = {0, 3568, 6112, 7632, 8128};

// Scratch (no allocations allowed)
__device__ float  g_par[KSPLIT][BB*NE*NE]; // raw gram partials (upper tiles)
__device__ float  g_sim[BB*NE*NE];         // fallback sim copy
__device__ float  g_rinv[BB][NE];          // 1/||emb_i||
__device__ double g_qs[BB][4][2];          // per-quarter fp64 {sum,sumsq}
__device__ float  g_cinv[BB];              // 1/(std+1e-5)
// counters: all return to 0 every launch (replay-safe)
__device__ int g_simcnt[BB];  // syrk arrivals (16)
__device__ int g_rdyq[BB];    // quarter rinv arrivals (4)
__device__ int g_rdyq2[BB];   // pass-2 (4) -> resets rdyq,rdyq2,simcnt
__device__ int g_scnt[BB];    // stats arrivals (4) -> last computes cinv
__device__ int g_ready[BB];   // cinv ready (1)
__device__ int g_rcnt[BB];    // ready consumers (4) -> resets ready,rcnt

// ---- acq/rel primitives ---------------------------------------------------
__device__ __forceinline__ void red_add_release(int* p, int v) {
    asm volatile("red.release.gpu.global.add.s32 [%0], %1;"
                 :: "l"(p), "r"(v) : "memory");
}
__device__ __forceinline__ int atom_add_acqrel(int* p, int v) {
    int r;
    asm volatile("atom.acq_rel.gpu.global.add.s32 %0, [%1], %2;"
                 : "=r"(r) : "l"(p), "r"(v) : "memory");
    return r;
}
__device__ __forceinline__ int ld_acquire(const int* p) {
    int r;
    asm volatile("ld.acquire.gpu.global.s32 %0, [%1];"
                 : "=r"(r) : "l"(p) : "memory");
    return r;
}
__device__ __forceinline__ void st_release(int* p, int v) {
    asm volatile("st.release.gpu.global.s32 [%0], %1;"
                 :: "l"(p), "r"(v) : "memory");
}

// ---- packed f32x2 helpers ------------------------------------------------
__device__ __forceinline__ void fma2(ull &d, ull a, ull b) {
    asm("fma.rn.f32x2 %0, %1, %2, %0;" : "+l"(d) : "l"(a), "l"(b));
}
__device__ __forceinline__ ull pack2(float v) {
    ull r; unsigned u = __float_as_uint(v);
    asm("mov.b64 %0, {%1, %1};" : "=l"(r) : "r"(u));
    return r;
}
__device__ __forceinline__ void unpack2(ull v, float &lo, float &hi) {
    unsigned a, b;
    asm("mov.b64 {%0, %1}, %2;" : "=r"(a), "=r"(b) : "l"(v));
    lo = __uint_as_float(a); hi = __uint_as_float(b);
}

// ---------------------------------------------------------------------------
__global__ void __launch_bounds__(TPB, 1)
k_all(const float* __restrict__ x,
      const int*   __restrict__ starts,
      const int*   __restrict__ lengths,
      const int*   __restrict__ hts,
      const float* __restrict__ thr,
      const float* __restrict__ W1,
      const float* __restrict__ b1,
      const float* __restrict__ W2,
      const float* __restrict__ b2,
      float*       __restrict__ out) {
    const int blk = blockIdx.x;           // 0..127
    const int b   = blk >> 4;             // batch
    const int kc  = blk & 15;             // k-chunk
    const int tid = threadIdx.x;          // 512

    __shared__ __align__(16) float At[KC][PITCH];   // pool slice / reused as sim quarter
    float* sSim = &At[0][0];                         // 32x128 after syrk done
    __shared__ int    sSt[NE], sLn[NE];
    __shared__ float  sRi[NE];
    __shared__ float  r0[128], r1[128], r2[128], r3[128];
    __shared__ int    rf[128];
    __shared__ double sS16[16], sQ16[16];

    // ======= Phase A: gather-pool 48-float slice of all 128 spans ==========
    if (tid < NE) {
        sSt[tid] = starts[b*NE + tid];
        sLn[tid] = lengths[b*NE + tid];
    }
    __syncthreads();
    {
        const int grp = tid >> 4;         // 0..31
        const int c   = tid & 15;         // f4 slot (0..11 active)
        if (c < 12) {
            const float4* xb4 = (const float4*)x + (long)b*LL*NP4 + kc*KC4 + c;
            #pragma unroll
            for (int half = 0; half < 2; ++half) {
                const int sp0 = half*64 + grp;
                const int sp1 = sp0 + 32;
                const int s0 = sSt[sp0], l0 = sLn[sp0];
                const int s1 = sSt[sp1], l1 = sLn[sp1];
                const float4* p0 = xb4 + (long)s0*NP4;
                const float4* p1 = xb4 + (long)s1*NP4;
                float4 a0 = make_float4(0,0,0,0), a1 = a0;
                #pragma unroll
                for (int t = 0; t < 16; ++t) {
                    if (t < l0) { const float4 v = p0[(long)t*NP4]; a0.x+=v.x; a0.y+=v.y; a0.z+=v.z; a0.w+=v.w; }
                    if (t < l1) { const float4 v = p1[(long)t*NP4]; a1.x+=v.x; a1.y+=v.y; a1.z+=v.z; a1.w+=v.w; }
                }
                const float i0 = 1.0f / (float)l0;
                const float i1 = 1.0f / (float)l1;
                At[4*c+0][sp0] = a0.x*i0;  At[4*c+0][sp1] = a1.x*i1;
                At[4*c+1][sp0] = a0.y*i0;  At[4*c+1][sp1] = a1.y*i1;
                At[4*c+2][sp0] = a0.z*i0;  At[4*c+2][sp1] = a1.z*i1;
                At[4*c+3][sp0] = a0.w*i0;  At[4*c+3][sp1] = a1.w*i1;
            }
        }
    }
    __syncthreads();

    // ======= Phase B: upper-triangular FFMA2 syrk ==========================
    if (tid < NTILE) {
        const int tp = 135 - tid;
        const int m  = (int)((sqrtf((float)(8*tp + 1)) - 1.0f) * 0.5f);
        const int ty = 15 - m;
        const int tx = 15 - (tp - (m*(m+1)) / 2);
        const int i8 = ty*8, j8 = tx*8;

        ull c[8][4];
        #pragma unroll
        for (int r = 0; r < 8; ++r)
            #pragma unroll
            for (int q = 0; q < 4; ++q) c[r][q] = 0ull;

        #pragma unroll 4
        for (int kk = 0; kk < KC; ++kk) {
            const float4 alo = *(const float4*)&At[kk][i8];
            const float4 ahi = *(const float4*)&At[kk][i8 + 4];
            ull a2[8];
            a2[0]=pack2(alo.x); a2[1]=pack2(alo.y); a2[2]=pack2(alo.z); a2[3]=pack2(alo.w);
            a2[4]=pack2(ahi.x); a2[5]=pack2(ahi.y); a2[6]=pack2(ahi.z); a2[7]=pack2(ahi.w);
            const ulonglong2 bv0 = *(const ulonglong2*)&At[kk][j8];
            const ulonglong2 bv1 = *(const ulonglong2*)&At[kk][j8 + 4];
            ull bb[4] = {bv0.x, bv0.y, bv1.x, bv1.y};
            #pragma unroll
            for (int r = 0; r < 8; ++r)
                #pragma unroll
                for (int q = 0; q < 4; ++q) fma2(c[r][q], a2[r], bb[q]);
        }

        float* P = g_par[kc] + (long)b*NE*NE + i8*NE + j8;
        #pragma unroll
        for (int r = 0; r < 8; ++r) {
            float l0,h0,l1,h1,l2,h2,l3,h3;
            unpack2(c[r][0], l0, h0);
            unpack2(c[r][1], l1, h1);
            unpack2(c[r][2], l2, h2);
            unpack2(c[r][3], l3, h3);
            __stcg(&((float4*)(P + (long)r*NE))[0], make_float4(l0, h0, l1, h1));
            __stcg(&((float4*)(P + (long)r*NE))[1], make_float4(l2, h2, l3, h3));
        }
    }
    __syncthreads();
    if (tid == 0) red_add_release(&g_simcnt[b], 1);

    if (kc >= 4) return;                  // non-stats blocks are done

    // ======= Phase C (kc<4): MLP collapse while waiting ====================
    const int q = kc;
    if (tid < 128) {
        const float w1  = W1[tid];
        const float w20 = W2[2*tid], w21 = W2[2*tid+1];
        r0[tid] = (w1 > 0.f) ? w1*w20 : 0.f;
        r1[tid] = (w1 > 0.f) ? w1*w21 : 0.f;
        r2[tid] = (w1 < 0.f) ? w1*w20 : 0.f;
        r3[tid] = (w1 < 0.f) ? w1*w21 : 0.f;
        rf[tid] = (b1[tid] != 0.f) ? 1 : 0;
    }
    __syncthreads();
    #pragma unroll
    for (int o = 64; o > 0; o >>= 1) {
        if (tid < o) {
            r0[tid]+=r0[tid+o]; r1[tid]+=r1[tid+o];
            r2[tid]+=r2[tid+o]; r3[tid]+=r3[tid+o];
            rf[tid]|=rf[tid+o];
        }
        __syncthreads();
    }

    // ---- wait for all 16 syrk chunk blocks of this batch ----
    if (tid == 0) {
        while (ld_acquire(&g_simcnt[b]) < 16) __nanosleep(32);
    }
    __syncthreads();

    // ---- sum 16 partial planes for this quarter (2 f4/thread) ----
    float4 acc[2];
    #pragma unroll
    for (int it = 0; it < 2; ++it) {
        const int f = q*1024 + tid + it*512;
        float4 a = make_float4(0.f,0.f,0.f,0.f);
        #pragma unroll
        for (int k2 = 0; k2 < KSPLIT; ++k2) {
            const float4 v = __ldcg(&((const float4*)(g_par[k2] + (long)b*NE*NE))[f]);
            a.x+=v.x; a.y+=v.y; a.z+=v.z; a.w+=v.w;
        }
        acc[it] = a;
        const int i  = f >> 5;
        const int j0 = (f & 31) * 4;
        if (i >= j0 && i < j0 + 4) {     // diagonal -> rinv
            const float d = (i == j0) ? a.x : (i == j0+1) ? a.y : (i == j0+2) ? a.z : a.w;
            __stcg(&g_rinv[b][i], rsqrtf(fmaxf(d, 1e-16f)));
        }
    }
    __syncthreads();
    if (tid == 0) {
        red_add_release(&g_rdyq[b], 1);
        while (ld_acquire(&g_rdyq[b]) < 4) __nanosleep(32);
        const int a2 = atom_add_acqrel(&g_rdyq2[b], 1);
        if (a2 == 3) { g_rdyq[b] = 0; g_rdyq2[b] = 0; g_simcnt[b] = 0; }
    }
    __syncthreads();
    if (tid < NE) sRi[tid] = __ldcg(&g_rinv[b][tid]);
    __syncthreads();

    // ---- normalize, write sim (smem + global fallback), weighted stats ----
    float s = 0.f, qq = 0.f;
    #pragma unroll
    for (int it = 0; it < 2; ++it) {
        const int f  = q*1024 + tid + it*512;
        const int i  = f >> 5;
        const int j0 = (f & 31) * 4;
        const float ri = sRi[i];
        float4 v = acc[it];
        v.x *= ri * sRi[j0  ];
        v.y *= ri * sRi[j0+1];
        v.z *= ri * sRi[j0+2];
        v.w *= ri * sRi[j0+3];
        ((float4*)sSim)[(i - q*32)*32 + (f & 31)] = v;
        __stcg(&((float4*)(g_sim + (long)b*NE*NE))[f], v);
        const float wx = (j0   > i) ? 2.f : (j0   == i) ? 1.f : 0.f;
        const float wy = (j0+1 > i) ? 2.f : (j0+1 == i) ? 1.f : 0.f;
        const float wz = (j0+2 > i) ? 2.f : (j0+2 == i) ? 1.f : 0.f;
        const float ww = (j0+3 > i) ? 2.f : (j0+3 == i) ? 1.f : 0.f;
        s  += wx*v.x + wy*v.y + wz*v.z + ww*v.w;
        qq += wx*v.x*v.x + wy*v.y*v.y + wz*v.z*v.z + ww*v.w*v.w;
    }
    double ds = (double)s, dq = (double)qq;
    #pragma unroll
    for (int o = 16; o > 0; o >>= 1) {
        ds += __shfl_xor_sync(0xffffffffu, ds, o);
        dq += __shfl_xor_sync(0xffffffffu, dq, o);
    }
    if ((tid & 31) == 0) { sS16[tid >> 5] = ds; sQ16[tid >> 5] = dq; }
    __syncthreads();
    if (tid == 0) {
        double ts = 0.0, tq = 0.0;
        #pragma unroll
        for (int w = 0; w < 16; ++w) { ts += sS16[w]; tq += sQ16[w]; }
        g_qs[b][q][0] = ts;
        g_qs[b][q][1] = tq;
        const int a3 = atom_add_acqrel(&g_scnt[b], 1);
        if (a3 == 3) {                    // deterministic fixed-order combine
            double fs = 0.0, fq = 0.0;
            #pragma unroll
            for (int q2 = 0; q2 < 4; ++q2) { fs += g_qs[b][q2][0]; fq += g_qs[b][q2][1]; }
            const double n  = (double)(NE*NE);
            const double sd = sqrt((fq - fs*fs/n) / (n - 1.0));
            g_cinv[b] = 1.0f / ((float)sd + 1e-5f);
            g_scnt[b] = 0;
            st_release(&g_ready[b], 1);
        }
        while (ld_acquire(&g_ready[b]) == 0) __nanosleep(32);
        const int a4 = atom_add_acqrel(&g_rcnt[b], 1);
        if (a4 == 3) { g_rcnt[b] = 0; g_ready[b] = 0; }
    }
    __syncthreads();

    // ======= Phase E: classify this quarter's contiguous pair range ========
    {
        const float cinv = __ldcg(&g_cinv[b]);
        const float t0   = __ldg(thr);
        const float b20  = __ldg(&b2[0]), b21 = __ldg(&b2[1]);
        const int p0 = c_qoff[q], p1 = c_qoff[q+1];

        for (int p = p0 + tid; p < p1; p += TPB) {
            const int gp = b*NPAIR + p;
            const int2 ht = ((const int2*)hts)[gp];
            float sim;
            if ((ht.x >> 5) == q)
                sim = sSim[(ht.x - q*32)*NE + ht.y];
            else
                sim = __ldcg(&g_sim[(long)b*NE*NE + ht.x*NE + ht.y]);
            const float pv = (sim - t0) * cinv;
            float o0, o1;
            if (rf[0] == 0) {
                o0 = fmaf(pv, (pv > 0.f) ? r0[0] : r2[0], b20);
                o1 = fmaf(pv, (pv > 0.f) ? r1[0] : r3[0], b21);
            } else {
                o0 = b20; o1 = b21;
                for (int k = 0; k < 128; ++k) {
                    const float h = fmaxf(fmaf(pv, __ldg(&W1[k]), __ldg(&b1[k])), 0.f);
                    o0 = fmaf(h, __ldg(&W2[2*k  ]), o0);
                    o1 = fmaf(h, __ldg(&W2[2*k+1]), o1);
                }
            }
            ((float2*)out)[gp] = make_float2(o0, o1);
        }
    }
}

// ---------------------------------------------------------------------------
extern "C" void kernel_launch(void* const* d_in, const int* in_sizes, int n_in,
                              void* d_out, int out_size) {
    const float* x       = (const float*)d_in[0];
    const int*   starts  = (const int*)  d_in[1];
    const int*   lengths = (const int*)  d_in[2];
    const int*   hts     = (const int*)  d_in[3];
    const float* thr     = (const float*)d_in[4];
    const float* W1      = (const float*)d_in[5];
    const float* b1      = (const float*)d_in[6];
    const float* W2      = (const float*)d_in[7];
    const float* b2      = (const float*)d_in[8];
    float* out = (float*)d_out;

    k_all<<<BB*KSPLIT, TPB>>>(x, starts, lengths, hts, thr, W1, b1, W2, b2, out);
}